// round 16
// baseline (speedup 1.0000x reference)
#include <cuda_runtime.h>
#include <cuda_bf16.h>
#include <mma.h>
#include <cstdint>

using namespace nvcuda;

#define BDIM 8
#define TDIM 8192
#define KDIM 64
#define DDIM 128
#define SEGL 16
#define NSEG (BDIM * TDIM / SEGL)           // 4096 segments (16 steps each)
#define SUPL 16
#define NSUP (NSEG / SUPL)                  // 256 supersegments
#define SUP_PER_B (NSUP / BDIM)             // 32 per batch
#define GROWS 64
#define NGBLK (BDIM * TDIM / GROWS)         // 1024 gemm blocks
#define NSPLIT 512                          // presplit blocks

// ---------------- scratch (device globals; no allocation) ----------------
__device__ float  g_u[BDIM * TDIM * KDIM];        // raw x @ W^T
__device__ float4 g_segA[NSEG * KDIM];            // (Ar, Ai, Br, Bi)
__device__ float4 g_supA[NSUP * KDIM];            // superseg aggregates
__device__ float4 g_supPre[NSUP * KDIM];          // exclusive prefixes
__device__ float2 g_hstart[NSEG * KDIM];          // h at segment start
__device__ float  g_inv_sigma;
__device__ __nv_bfloat16 g_Whi[KDIM * DDIM];      // W split hi
__device__ __nv_bfloat16 g_Wlo[KDIM * DDIM];      // W split lo
__device__ __nv_bfloat16 g_Xhi[BDIM * TDIM * DDIM];  // x split hi (16.8MB)
__device__ __nv_bfloat16 g_Xlo[BDIM * TDIM * DDIM];  // x split lo

// pack 2 floats -> 2 bf16 hi and 2 bf16 lo words
__device__ __forceinline__ void split2(float a, float b, uint32_t& hw, uint32_t& lw) {
    __nv_bfloat16 h0 = __float2bfloat16(a);
    __nv_bfloat16 h1 = __float2bfloat16(b);
    __nv_bfloat16 l0 = __float2bfloat16(a - __bfloat162float(h0));
    __nv_bfloat16 l1 = __float2bfloat16(b - __bfloat162float(h1));
    hw = ((uint32_t)__bfloat16_as_ushort(h1) << 16) | __bfloat16_as_ushort(h0);
    lw = ((uint32_t)__bfloat16_as_ushort(l1) << 16) | __bfloat16_as_ushort(l0);
}

// =========================================================================
// Kernel 0: split x and W into global bf16 hi/lo. Grid NSPLIT x 256.
// Block 0 additionally splits W (8192 elements).
// =========================================================================
__global__ __launch_bounds__(256) void presplit_kernel(
    const float* __restrict__ x, const float* __restrict__ W)
{
    const int tid = threadIdx.x;

    if (blockIdx.x == 0) {
        #pragma unroll
        for (int i = 0; i < KDIM * DDIM / 512; i++) {   // 16 iters, 2 elts each
            int e = (tid + 256 * i) * 2;
            uint32_t hw, lw;
            split2(W[e], W[e + 1], hw, lw);
            *(uint32_t*)&g_Whi[e] = hw;
            *(uint32_t*)&g_Wlo[e] = lw;
        }
    }

    // x: 8.39M elements over 512 blocks x 256 threads = 64 per thread
    const size_t NTOT = (size_t)BDIM * TDIM * DDIM;      // 8388608
    const size_t nf4  = NTOT / 4;                        // 2097152 float4
    const float4* xb = (const float4*)x;
    size_t idx0 = (size_t)blockIdx.x * 256 + tid;
    #pragma unroll 4
    for (size_t i = idx0; i < nf4; i += (size_t)NSPLIT * 256) {
        float4 v = xb[i];
        uint32_t h0, l0, h1, l1;
        split2(v.x, v.y, h0, l0);
        split2(v.z, v.w, h1, l1);
        *(uint2*)&g_Xhi[i * 4] = make_uint2(h0, h1);
        *(uint2*)&g_Xlo[i * 4] = make_uint2(l0, l1);
    }
}

// =========================================================================
// Kernel 1: u = x@W^T, smem-free wmma (A and B fragments from global/L1)
// + sigma block 0. Grid 1 + 1024; 128 threads (4 warps x 16 rows).
// =========================================================================
__global__ __launch_bounds__(128)
void gemm_wmma_kernel(const float* __restrict__ W)
{
    __shared__ float sig[4288];      // only block 0 touches (Ms + v0 + v1)
    const int tid = threadIdx.x;

    if (blockIdx.x == 0) {
        float* Ms = sig;             // [64][65]
        float* v0 = Ms + 4160;
        float* v1 = v0 + 64;
        for (int e = tid; e < 4096; e += 128) {
            int r = e >> 6, c = e & 63;
            const float4* a = (const float4*)(W + r * DDIM);
            const float4* b = (const float4*)(W + c * DDIM);
            float s = 0.f;
            #pragma unroll
            for (int d = 0; d < 32; d++) {
                float4 av = a[d], bv = b[d];
                s += av.x*bv.x + av.y*bv.y + av.z*bv.z + av.w*bv.w;
            }
            Ms[r*65 + c] = s;
        }
        if (tid < 64) v0[tid] = 1.0f;
        __syncthreads();
        const int r = tid >> 1, part = tid & 1;
        float* va = v0; float* vb = v1;
        for (int it = 0; it < 96; it++) {
            float s = 0.f;
            #pragma unroll
            for (int j = 0; j < 32; j++)
                s += Ms[r*65 + part*32 + j] * va[part*32 + j];
            s += __shfl_xor_sync(0xffffffffu, s, 1);
            if (part == 0) vb[r] = ((it & 31) == 31) ? s * 1e-14f : s;
            __syncthreads();
            float* t = va; va = vb; vb = t;
        }
        {   // Rayleigh quotient
            float s = 0.f;
            #pragma unroll
            for (int j = 0; j < 32; j++)
                s += Ms[r*65 + part*32 + j] * va[part*32 + j];
            s += __shfl_xor_sync(0xffffffffu, s, 1);
            if (part == 0) vb[r] = s;
        }
        __syncthreads();
        if (tid == 0) {
            float num = 0.f, den = 0.f;
            for (int j = 0; j < 64; j++) { num += va[j]*vb[j]; den += va[j]*va[j]; }
            g_inv_sigma = 1.0f / sqrtf(num / den);
        }
        return;
    }

    const int row0 = (blockIdx.x - 1) * GROWS;
    const int w = tid >> 5;
    const int arow = row0 + w * 16;

    wmma::fragment<wmma::accumulator, 16, 16, 16, float> fc[4];
    #pragma unroll
    for (int nt = 0; nt < 4; nt++) wmma::fill_fragment(fc[nt], 0.0f);

    wmma::fragment<wmma::matrix_a, 16, 16, 16, __nv_bfloat16, wmma::row_major> fahi, falo;
    wmma::fragment<wmma::matrix_b, 16, 16, 16, __nv_bfloat16, wmma::col_major> fbhi, fblo;

    const __nv_bfloat16* Ah = g_Xhi + (size_t)arow * DDIM;
    const __nv_bfloat16* Al = g_Xlo + (size_t)arow * DDIM;

    #pragma unroll
    for (int kk = 0; kk < 8; kk++) {
        wmma::load_matrix_sync(fahi, Ah + kk * 16, DDIM);
        wmma::load_matrix_sync(falo, Al + kk * 16, DDIM);
        #pragma unroll
        for (int nt = 0; nt < 4; nt++) {
            wmma::load_matrix_sync(fbhi, g_Whi + (nt * 16) * DDIM + kk * 16, DDIM);
            wmma::mma_sync(fc[nt], fahi, fbhi, fc[nt]);   // hi*hi
            wmma::mma_sync(fc[nt], falo, fbhi, fc[nt]);   // lo*hi
            wmma::load_matrix_sync(fblo, g_Wlo + (nt * 16) * DDIM + kk * 16, DDIM);
            wmma::mma_sync(fc[nt], fahi, fblo, fc[nt]);   // hi*lo
        }
    }

    float* outp = &g_u[(size_t)arow * KDIM];
    #pragma unroll
    for (int nt = 0; nt < 4; nt++)
        wmma::store_matrix_sync(outp + nt * 16, fc[nt], KDIM, wmma::mem_row_major);
}

// =========================================================================
// Kernel 2: per-segment aggregates, sigma+bias folded in. Grid 1024 x 256.
// =========================================================================
__global__ __launch_bounds__(256) void aggregate_kernel(
    const float* __restrict__ dt,   const float* __restrict__ amod,
    const float* __restrict__ omod, const float* __restrict__ tmod,
    const float* __restrict__ srr,  const float* __restrict__ sim,
    const float* __restrict__ traw, const float* __restrict__ bias)
{
    const int tid = threadIdx.x;
    const int k   = tid & 63;
    const int seg = blockIdx.x * 4 + (tid >> 6);
    const int t0  = seg * SEGL;

    float tr  = traw[0];
    float tau = ((tr > 20.f) ? tr : log1pf(expf(tr))) + 1e-3f;
    float sr  = srr[k];
    float sp  = (sr > 20.f) ? sr : log1pf(expf(sr));
    float alpha0 = (sp + 1e-6f) * tau;
    float omega0 = sim[k] * tau;
    float bk     = bias[k];
    float invsig = g_inv_sigma;

    float cr[SEGL], ci[SEGL], uu[SEGL];
    #pragma unroll
    for (int i = 0; i < SEGL; i++) {
        int bt = t0 + i;
        size_t idx = (size_t)bt * KDIM + k;
        float tv  = tmod[bt];
        float dtv = dt[bt];
        float alpha = alpha0 * __expf(amod[idx] + tv);
        float omega = omega0 * __expf(omod[idx] + tv);
        float rho   = __expf(-alpha * dtv);
        float sn, cs; __sincosf(omega * dtv, &sn, &cs);
        cr[i] = rho * cs; ci[i] = rho * sn;
        uu[i] = g_u[idx] * invsig + bk;
    }

    float Ar = 1.f, Ai = 0.f, Br = 0.f, Bi = 0.f;
    #pragma unroll
    for (int i = 0; i < SEGL; i++) {
        float car = cr[i], cai = ci[i];
        float nbr = car*Br - cai*Bi + uu[i];
        float nbi = car*Bi + cai*Br;
        float nar = car*Ar - cai*Ai;
        float nai = car*Ai + cai*Ar;
        Br = nbr; Bi = nbi; Ar = nar; Ai = nai;
    }
    g_segA[(size_t)seg * KDIM + k] = make_float4(Ar, Ai, Br, Bi);
}

// =========================================================================
// Kernel 3a: superseg aggregates (combine 16 segAs). Grid 64 x 256.
// =========================================================================
__global__ __launch_bounds__(256) void superagg_kernel()
{
    const int tid = threadIdx.x;
    const int k   = tid & 63;
    const int sup = blockIdx.x * 4 + (tid >> 6);
    const size_t base = (size_t)sup * SUPL * KDIM + k;

    float4 v[SUPL];
    #pragma unroll
    for (int j = 0; j < SUPL; j++) v[j] = g_segA[base + (size_t)j * KDIM];

    float Ar = 1.f, Ai = 0.f, Br = 0.f, Bi = 0.f;
    #pragma unroll
    for (int j = 0; j < SUPL; j++) {
        float nAr = v[j].x*Ar - v[j].y*Ai;
        float nAi = v[j].x*Ai + v[j].y*Ar;
        float nBr = v[j].x*Br - v[j].y*Bi + v[j].z;
        float nBi = v[j].x*Bi + v[j].y*Br + v[j].w;
        Ar = nAr; Ai = nAi; Br = nBr; Bi = nBi;
    }
    g_supA[(size_t)sup * KDIM + k] = make_float4(Ar, Ai, Br, Bi);
}

// =========================================================================
// Kernel 3b: exclusive scan of 32 supersegs per (batch, k). Grid 8 x 64.
// =========================================================================
__global__ __launch_bounds__(64) void topscan_kernel()
{
    const int k = threadIdx.x;
    const int b = blockIdx.x;
    const size_t base = (size_t)b * SUP_PER_B * KDIM + k;

    float EAr = 1.f, EAi = 0.f, EBr = 0.f, EBi = 0.f;
    #pragma unroll
    for (int half = 0; half < 2; half++) {
        float4 v[16];
        #pragma unroll
        for (int j = 0; j < 16; j++)
            v[j] = g_supA[base + (size_t)(half * 16 + j) * KDIM];
        #pragma unroll
        for (int j = 0; j < 16; j++) {
            g_supPre[base + (size_t)(half * 16 + j) * KDIM] =
                make_float4(EAr, EAi, EBr, EBi);
            float nAr = v[j].x*EAr - v[j].y*EAi;
            float nAi = v[j].x*EAi + v[j].y*EAr;
            float nBr = v[j].x*EBr - v[j].y*EBi + v[j].z;
            float nBi = v[j].x*EBi + v[j].y*EBr + v[j].w;
            EAr = nAr; EAi = nAi; EBr = nBr; EBi = nBi;
        }
    }
}

// =========================================================================
// Kernel 3c: expand superseg prefixes to per-segment h_start. Grid 64 x 256.
// =========================================================================
__global__ __launch_bounds__(256) void hstart_kernel()
{
    const int tid = threadIdx.x;
    const int k   = tid & 63;
    const int sup = blockIdx.x * 4 + (tid >> 6);
    const size_t base = (size_t)sup * SUPL * KDIM + k;

    float4 v[SUPL];
    #pragma unroll
    for (int j = 0; j < SUPL; j++) v[j] = g_segA[base + (size_t)j * KDIM];

    float4 E = g_supPre[(size_t)sup * KDIM + k];
    float EAr = E.x, EAi = E.y, EBr = E.z, EBi = E.w;
    #pragma unroll
    for (int j = 0; j < SUPL; j++) {
        g_hstart[base + (size_t)j * KDIM] = make_float2(EBr, EBi);   // h0 = 0
        float nAr = v[j].x*EAr - v[j].y*EAi;
        float nAi = v[j].x*EAi + v[j].y*EAr;
        float nBr = v[j].x*EBr - v[j].y*EBi + v[j].z;
        float nBi = v[j].x*EBi + v[j].y*EBr + v[j].w;
        EAr = nAr; EAi = nAi; EBr = nBr; EBi = nBi;
    }
}

// =========================================================================
// Kernel 4: apply pass. Thread = (segment, k). Prefetch-then-chain.
// =========================================================================
__global__ __launch_bounds__(256) void apply_kernel(
    const float* __restrict__ dt,   const float* __restrict__ amod,
    const float* __restrict__ omod, const float* __restrict__ tmod,
    const float* __restrict__ srr,  const float* __restrict__ sim,
    const float* __restrict__ traw, const float* __restrict__ bias,
    float* __restrict__ out)
{
    const int tid = threadIdx.x;
    const int k   = tid & 63;
    const int seg = blockIdx.x * 4 + (tid >> 6);
    const int t0  = seg * SEGL;

    float tr  = traw[0];
    float tau = ((tr > 20.f) ? tr : log1pf(expf(tr))) + 1e-3f;
    float sr  = srr[k];
    float sp  = (sr > 20.f) ? sr : log1pf(expf(sr));
    float alpha0 = (sp + 1e-6f) * tau;
    float omega0 = sim[k] * tau;
    float bk     = bias[k];
    float invsig = g_inv_sigma;

    float cr[SEGL], ci[SEGL], uu[SEGL];
    #pragma unroll
    for (int i = 0; i < SEGL; i++) {
        int bt = t0 + i;
        size_t idx = (size_t)bt * KDIM + k;
        float tv  = tmod[bt];
        float dtv = dt[bt];
        float alpha = alpha0 * __expf(amod[idx] + tv);
        float omega = omega0 * __expf(omod[idx] + tv);
        float rho   = __expf(-alpha * dtv);
        float sn, cs; __sincosf(omega * dtv, &sn, &cs);
        cr[i] = rho * cs; ci[i] = rho * sn;
        uu[i] = g_u[idx] * invsig + bk;
    }

    float2 h = g_hstart[(size_t)seg * KDIM + k];
    float hr = h.x, hi = h.y;

    #pragma unroll
    for (int i = 0; i < SEGL; i++) {
        float nr = cr[i]*hr - ci[i]*hi + uu[i];
        float ni = cr[i]*hi + ci[i]*hr;
        hr = nr; hi = ni;
        size_t ob = (size_t)(t0 + i) * (2 * KDIM);
        out[ob + k]        = hr;   // C
        out[ob + KDIM + k] = hi;   // S
    }
}

// =========================================================================
extern "C" void kernel_launch(void* const* d_in, const int* in_sizes, int n_in,
                              void* d_out, int out_size)
{
    (void)in_sizes; (void)n_in; (void)out_size;
    const float* x    = (const float*)d_in[0];
    const float* dt   = (const float*)d_in[1];
    const float* amod = (const float*)d_in[2];
    const float* omod = (const float*)d_in[3];
    const float* tmod = (const float*)d_in[4];
    const float* srr  = (const float*)d_in[5];
    const float* sim  = (const float*)d_in[6];
    const float* traw = (const float*)d_in[7];
    const float* W    = (const float*)d_in[8];
    const float* bias = (const float*)d_in[9];
    float* out = (float*)d_out;

    presplit_kernel<<<NSPLIT, 256>>>(x, W);
    gemm_wmma_kernel<<<NGBLK + 1, 128>>>(W);
    aggregate_kernel<<<NSEG / 4, 256>>>(dt, amod, omod, tmod, srr, sim, traw, bias);
    superagg_kernel<<<NSUP / 4, 256>>>();
    topscan_kernel<<<BDIM, 64>>>();
    hstart_kernel<<<NSUP / 4, 256>>>();
    apply_kernel<<<NSEG / 4, 256>>>(dt, amod, omod, tmod, srr, sim, traw, bias, out);
}